// round 1
// baseline (speedup 1.0000x reference)
#include <cuda_runtime.h>
#include <math.h>

// ---------------- problem constants ----------------
#define BATCH   2
#define SEQ     2048
#define HID     768
#define NST     64
#define NLAYER  6
#define VOCAB   32000
#define MROWS   (BATCH*SEQ)          // 4096
#define FFN     (4*HID)              // 3072
#define EPSLN   1e-5f

// ---------------- scratch (device globals; no malloc allowed) ----------------
__device__ float g_h  [MROWS*HID];        // residual stream [B,S,H]
__device__ float g_x  [MROWS*HID];        // LN output (normal layout)
__device__ float g_xT [BATCH*HID*SEQ];    // LN1 output transposed [B,H,S]
__device__ float g_mid[MROWS*FFN];        // MLP intermediate

// ---------------- embedding gather ----------------
__global__ void embed_kernel(const int* __restrict__ tokens,
                             const float* __restrict__ emb,
                             float* __restrict__ out)
{
    int e = blockIdx.x * blockDim.x + threadIdx.x;
    if (e >= MROWS*HID) return;
    int row = e / HID, c = e - row*HID;
    out[e] = emb[(size_t)tokens[row]*HID + c];
}

// ---------------- layernorm (one block per row, 256 threads, H=768=3*256) ----
__global__ void ln_kernel(const float* __restrict__ in, float* __restrict__ out,
                          const float* __restrict__ w, const float* __restrict__ b,
                          int transpose_out)
{
    int row = blockIdx.x;
    int tid = threadIdx.x;
    const float* xr = in + (size_t)row*HID;
    float x0 = xr[tid], x1 = xr[tid+256], x2 = xr[tid+512];

    __shared__ float red[256];
    red[tid] = x0 + x1 + x2;
    __syncthreads();
    #pragma unroll
    for (int s = 128; s > 0; s >>= 1) {
        if (tid < s) red[tid] += red[tid+s];
        __syncthreads();
    }
    float mean = red[0] * (1.0f/HID);
    __syncthreads();

    float d0 = x0-mean, d1 = x1-mean, d2 = x2-mean;
    red[tid] = d0*d0 + d1*d1 + d2*d2;
    __syncthreads();
    #pragma unroll
    for (int s = 128; s > 0; s >>= 1) {
        if (tid < s) red[tid] += red[tid+s];
        __syncthreads();
    }
    float rstd = rsqrtf(red[0]*(1.0f/HID) + EPSLN);

    float o0 = d0*rstd*w[tid    ] + b[tid    ];
    float o1 = d1*rstd*w[tid+256] + b[tid+256];
    float o2 = d2*rstd*w[tid+512] + b[tid+512];

    if (!transpose_out) {
        float* orow = out + (size_t)row*HID;
        orow[tid] = o0; orow[tid+256] = o1; orow[tid+512] = o2;
    } else {
        int bb = row / SEQ, t = row - bb*SEQ;        // out[b][h][t]
        size_t base = (size_t)bb*HID*SEQ + t;
        out[base + (size_t)(tid    )*SEQ] = o0;
        out[base + (size_t)(tid+256)*SEQ] = o1;
        out[base + (size_t)(tid+512)*SEQ] = o2;
    }
}

// ---------------- S4D scan: one warp per (b,h); 2 states per lane -----------
// x is transposed [B,H,S]; result is ADDED into hres [B,S,H] (residual).
__global__ void __launch_bounds__(256) s4d_kernel(
    const float* __restrict__ xT, float* __restrict__ hres,
    const float* __restrict__ A_log, const float* __restrict__ Bm,
    const float* __restrict__ Cm, const float* __restrict__ log_dt, int layer)
{
    int gwarp = (blockIdx.x * blockDim.x + threadIdx.x) >> 5;
    int lane  = threadIdx.x & 31;
    int w     = threadIdx.x >> 5;
    if (gwarp >= BATCH*HID) return;
    int b = gwarp / HID, h = gwarp - b*HID;

    float dtv = expf(log_dt[layer*HID + h]);
    int n0 = lane, n1 = lane + 32;
    float A0 = expf(-dtv * expf(A_log[layer*NST + n0]));
    float A1 = expf(-dtv * expf(A_log[layer*NST + n1]));
    size_t pbase = ((size_t)layer*HID + h) * NST;
    float B0 = dtv * Bm[pbase + n0];
    float B1 = dtv * Bm[pbase + n1];
    float C0 = Cm[pbase + n0];
    float C1 = Cm[pbase + n1];

    __shared__ float sh[8][32][33];

    const float* xrow = xT + ((size_t)b*HID + h) * SEQ;
    float*       hout = hres + (size_t)b*SEQ*HID + h;

    float s0 = 0.f, s1 = 0.f;
    for (int t0 = 0; t0 < SEQ; t0 += 32) {
        float xv = xrow[t0 + lane];
        #pragma unroll
        for (int i = 0; i < 32; i++) {
            float xt = __shfl_sync(0xffffffffu, xv, i);
            s0 = fmaf(A0, s0, B0 * xt);
            s1 = fmaf(A1, s1, B1 * xt);
            sh[w][i][lane] = fmaf(s0, C0, s1 * C1);
        }
        __syncwarp();
        float acc = 0.f;
        #pragma unroll
        for (int j = 0; j < 32; j++) acc += sh[w][lane][j];
        hout[(size_t)(t0 + lane) * HID] += acc;
        __syncwarp();
    }
}

// ---------------- GEMM: C[M,Nc] = A[M,K] * B, fp32 SIMT tiled ----------------
// BMODE 0: B is [K,Nc] (NN).  BMODE 1: B is [Nc,K] (NT, row dot row).
// EPI 0: C = acc. EPI 1: C = gelu(acc + bias). EPI 2: C += acc + bias.
__device__ __forceinline__ float gelu_exact(float x) {
    return 0.5f * x * (1.0f + erff(x * 0.70710678118654752440f));
}

template<int BMODE, int EPI>
__global__ void __launch_bounds__(256) gemm_kernel(
    const float* __restrict__ A, const float* __restrict__ B,
    const float* __restrict__ bias, float* __restrict__ C,
    int M, int Nc, int K)
{
    __shared__ float As[8][128];
    __shared__ float Bs[8][128];
    const int tid = threadIdx.x;
    const int bm = blockIdx.y * 128;
    const int bn = blockIdx.x * 128;

    const int arow = tid >> 1;
    const int akg  = (tid & 1) * 4;
    const float* Aptr = A + (size_t)(bm + arow) * K + akg;

    const int bkr  = tid >> 5;
    const int bcol = (tid & 31) * 4;
    const float* BptrNN = B + (size_t)bkr * Nc + bn + bcol;
    const float* BptrNT = B + (size_t)(bn + arow) * K + akg;

    const int rowb = (tid >> 4) * 8;
    const int colb = (tid & 15) * 8;

    float acc[8][8];
    #pragma unroll
    for (int i = 0; i < 8; i++)
        #pragma unroll
        for (int j = 0; j < 8; j++) acc[i][j] = 0.f;

    for (int k0 = 0; k0 < K; k0 += 8) {
        float4 av = *(const float4*)Aptr; Aptr += 8;
        As[akg+0][arow] = av.x; As[akg+1][arow] = av.y;
        As[akg+2][arow] = av.z; As[akg+3][arow] = av.w;
        if (BMODE == 1) {
            float4 bv = *(const float4*)BptrNT; BptrNT += 8;
            Bs[akg+0][arow] = bv.x; Bs[akg+1][arow] = bv.y;
            Bs[akg+2][arow] = bv.z; Bs[akg+3][arow] = bv.w;
        } else {
            float4 bv = *(const float4*)BptrNN; BptrNN += (size_t)8 * Nc;
            *(float4*)&Bs[bkr][bcol] = bv;
        }
        __syncthreads();
        #pragma unroll
        for (int k = 0; k < 8; k++) {
            float a[8], bb[8];
            *(float4*)(a  )  = *(const float4*)&As[k][rowb];
            *(float4*)(a+4)  = *(const float4*)&As[k][rowb+4];
            *(float4*)(bb  ) = *(const float4*)&Bs[k][colb];
            *(float4*)(bb+4) = *(const float4*)&Bs[k][colb+4];
            #pragma unroll
            for (int i = 0; i < 8; i++)
                #pragma unroll
                for (int j = 0; j < 8; j++)
                    acc[i][j] = fmaf(a[i], bb[j], acc[i][j]);
        }
        __syncthreads();
    }

    float bvv[8];
    if (EPI != 0) {
        #pragma unroll
        for (int j = 0; j < 8; j++) bvv[j] = bias[bn + colb + j];
    }
    #pragma unroll
    for (int i = 0; i < 8; i++) {
        float* crow = C + (size_t)(bm + rowb + i) * Nc + bn + colb;
        if (EPI == 0) {
            float4 o0 = make_float4(acc[i][0], acc[i][1], acc[i][2], acc[i][3]);
            float4 o1 = make_float4(acc[i][4], acc[i][5], acc[i][6], acc[i][7]);
            *(float4*)(crow)   = o0;
            *(float4*)(crow+4) = o1;
        } else if (EPI == 1) {
            float4 o0, o1;
            o0.x = gelu_exact(acc[i][0] + bvv[0]);
            o0.y = gelu_exact(acc[i][1] + bvv[1]);
            o0.z = gelu_exact(acc[i][2] + bvv[2]);
            o0.w = gelu_exact(acc[i][3] + bvv[3]);
            o1.x = gelu_exact(acc[i][4] + bvv[4]);
            o1.y = gelu_exact(acc[i][5] + bvv[5]);
            o1.z = gelu_exact(acc[i][6] + bvv[6]);
            o1.w = gelu_exact(acc[i][7] + bvv[7]);
            *(float4*)(crow)   = o0;
            *(float4*)(crow+4) = o1;
        } else {
            float4 c0 = *(float4*)(crow);
            float4 c1 = *(float4*)(crow+4);
            c0.x += acc[i][0] + bvv[0]; c0.y += acc[i][1] + bvv[1];
            c0.z += acc[i][2] + bvv[2]; c0.w += acc[i][3] + bvv[3];
            c1.x += acc[i][4] + bvv[4]; c1.y += acc[i][5] + bvv[5];
            c1.z += acc[i][6] + bvv[6]; c1.w += acc[i][7] + bvv[7];
            *(float4*)(crow)   = c0;
            *(float4*)(crow+4) = c1;
        }
    }
}

// ---------------- driver ----------------
extern "C" void kernel_launch(void* const* d_in, const int* in_sizes, int n_in,
                              void* d_out, int out_size)
{
    const int*   tokens = (const int*)  d_in[0];
    const float* emb    = (const float*)d_in[1];
    const float* ln1_w  = (const float*)d_in[2];
    const float* ln1_b  = (const float*)d_in[3];
    const float* A_log  = (const float*)d_in[4];
    const float* Bm     = (const float*)d_in[5];
    const float* Cm     = (const float*)d_in[6];
    const float* log_dt = (const float*)d_in[7];
    const float* ln2_w  = (const float*)d_in[8];
    const float* ln2_b  = (const float*)d_in[9];
    const float* W1     = (const float*)d_in[10];
    const float* b1     = (const float*)d_in[11];
    const float* W2     = (const float*)d_in[12];
    const float* b2     = (const float*)d_in[13];
    const float* lnf_w  = (const float*)d_in[14];
    const float* lnf_b  = (const float*)d_in[15];
    float* out = (float*)d_out;

    float *ph, *px, *pxT, *pmid;
    cudaGetSymbolAddress((void**)&ph,   g_h);
    cudaGetSymbolAddress((void**)&px,   g_x);
    cudaGetSymbolAddress((void**)&pxT,  g_xT);
    cudaGetSymbolAddress((void**)&pmid, g_mid);

    // embedding
    embed_kernel<<<(MROWS*HID + 255)/256, 256>>>(tokens, emb, ph);

    for (int l = 0; l < NLAYER; l++) {
        // LN1 -> transposed [B,H,S]
        ln_kernel<<<MROWS, 256>>>(ph, pxT, ln1_w + l*HID, ln1_b + l*HID, 1);
        // S4D scan, adds into residual
        s4d_kernel<<<(BATCH*HID*32 + 255)/256, 256>>>(pxT, ph, A_log, Bm, Cm, log_dt, l);
        // LN2 -> normal layout
        ln_kernel<<<MROWS, 256>>>(ph, px, ln2_w + l*HID, ln2_b + l*HID, 0);
        // MLP up: gelu(x @ W1 + b1)
        gemm_kernel<0,1><<<dim3(FFN/128, MROWS/128), 256>>>(
            px, W1 + (size_t)l*HID*FFN, b1 + (size_t)l*FFN, pmid, MROWS, FFN, HID);
        // MLP down + residual: h += mid @ W2 + b2
        gemm_kernel<0,2><<<dim3(HID/128, MROWS/128), 256>>>(
            pmid, W2 + (size_t)l*FFN*HID, b2 + (size_t)l*HID, ph, MROWS, HID, FFN);
    }

    // final LN + tied head (NT: logits = x @ embed^T)
    ln_kernel<<<MROWS, 256>>>(ph, px, lnf_w, lnf_b, 0);
    gemm_kernel<1,0><<<dim3(VOCAB/128, MROWS/128), 256>>>(
        px, emb, nullptr, out, MROWS, VOCAB, HID);
}

// round 2
// speedup vs baseline: 2.6815x; 2.6815x over previous
#include <cuda_runtime.h>
#include <math.h>
#include <stdint.h>

// ---------------- problem constants ----------------
#define BATCH   2
#define SEQ     2048
#define HID     768
#define NST     64
#define NLAYER  6
#define VOCAB   32000
#define MROWS   (BATCH*SEQ)          // 4096
#define FFN     (4*HID)              // 3072
#define EPSLN   1e-5f

// ---------------- scratch (device globals; no malloc allowed) ----------------
__device__ float g_h  [MROWS*HID];        // residual stream [B,S,H]
__device__ float g_x  [MROWS*HID];        // LN output (normal layout)
__device__ float g_xT [BATCH*HID*SEQ];    // LN1 output transposed [B,H,S]
__device__ float g_mid[MROWS*FFN];        // MLP intermediate

// ---------------- embedding gather ----------------
__global__ void embed_kernel(const int* __restrict__ tokens,
                             const float* __restrict__ emb,
                             float* __restrict__ out)
{
    int e = blockIdx.x * blockDim.x + threadIdx.x;
    if (e >= MROWS*HID) return;
    int row = e / HID, c = e - row*HID;
    out[e] = emb[(size_t)tokens[row]*HID + c];
}

// ---------------- layernorm (one block per row, 256 threads, H=768=3*256) ----
__global__ void ln_kernel(const float* __restrict__ in, float* __restrict__ out,
                          const float* __restrict__ w, const float* __restrict__ b,
                          int transpose_out)
{
    int row = blockIdx.x;
    int tid = threadIdx.x;
    const float* xr = in + (size_t)row*HID;
    float x0 = xr[tid], x1 = xr[tid+256], x2 = xr[tid+512];

    __shared__ float red[256];
    red[tid] = x0 + x1 + x2;
    __syncthreads();
    #pragma unroll
    for (int s = 128; s > 0; s >>= 1) {
        if (tid < s) red[tid] += red[tid+s];
        __syncthreads();
    }
    float mean = red[0] * (1.0f/HID);
    __syncthreads();

    float d0 = x0-mean, d1 = x1-mean, d2 = x2-mean;
    red[tid] = d0*d0 + d1*d1 + d2*d2;
    __syncthreads();
    #pragma unroll
    for (int s = 128; s > 0; s >>= 1) {
        if (tid < s) red[tid] += red[tid+s];
        __syncthreads();
    }
    float rstd = rsqrtf(red[0]*(1.0f/HID) + EPSLN);

    float o0 = d0*rstd*w[tid    ] + b[tid    ];
    float o1 = d1*rstd*w[tid+256] + b[tid+256];
    float o2 = d2*rstd*w[tid+512] + b[tid+512];

    if (!transpose_out) {
        float* orow = out + (size_t)row*HID;
        orow[tid] = o0; orow[tid+256] = o1; orow[tid+512] = o2;
    } else {
        int bb = row / SEQ, t = row - bb*SEQ;        // out[b][h][t]
        size_t base = (size_t)bb*HID*SEQ + t;
        out[base + (size_t)(tid    )*SEQ] = o0;
        out[base + (size_t)(tid+256)*SEQ] = o1;
        out[base + (size_t)(tid+512)*SEQ] = o2;
    }
}

// ---------------- S4D scan: one warp per (b,h); 2 states per lane -----------
__global__ void __launch_bounds__(256) s4d_kernel(
    const float* __restrict__ xT, float* __restrict__ hres,
    const float* __restrict__ A_log, const float* __restrict__ Bm,
    const float* __restrict__ Cm, const float* __restrict__ log_dt, int layer)
{
    int gwarp = (blockIdx.x * blockDim.x + threadIdx.x) >> 5;
    int lane  = threadIdx.x & 31;
    int w     = threadIdx.x >> 5;
    if (gwarp >= BATCH*HID) return;
    int b = gwarp / HID, h = gwarp - b*HID;

    float dtv = expf(log_dt[layer*HID + h]);
    int n0 = lane, n1 = lane + 32;
    float A0 = expf(-dtv * expf(A_log[layer*NST + n0]));
    float A1 = expf(-dtv * expf(A_log[layer*NST + n1]));
    size_t pbase = ((size_t)layer*HID + h) * NST;
    float B0 = dtv * Bm[pbase + n0];
    float B1 = dtv * Bm[pbase + n1];
    float C0 = Cm[pbase + n0];
    float C1 = Cm[pbase + n1];

    __shared__ float sh[8][32][33];

    const float* xrow = xT + ((size_t)b*HID + h) * SEQ;
    float*       hout = hres + (size_t)b*SEQ*HID + h;

    float s0 = 0.f, s1 = 0.f;
    for (int t0 = 0; t0 < SEQ; t0 += 32) {
        float xv = xrow[t0 + lane];
        #pragma unroll
        for (int i = 0; i < 32; i++) {
            float xt = __shfl_sync(0xffffffffu, xv, i);
            s0 = fmaf(A0, s0, B0 * xt);
            s1 = fmaf(A1, s1, B1 * xt);
            sh[w][i][lane] = fmaf(s0, C0, s1 * C1);
        }
        __syncwarp();
        float acc = 0.f;
        #pragma unroll
        for (int j = 0; j < 32; j++) acc += sh[w][lane][j];
        hout[(size_t)(t0 + lane) * HID] += acc;
        __syncwarp();
    }
}

// ---------------- TF32 tensor-core GEMM --------------------------------------
// C[M,Nc] = A[M,K] @ B.  BMODE 0: B[K,Nc] (NN). BMODE 1: B[Nc,K] (NT).
// EPI 0: C=acc. EPI 1: C=gelu(acc+bias). EPI 2: C += acc+bias (residual).
// CTA: 128x128xK, BK=16, 4 warps, warp tile 64x64, mma.m16n8k8.tf32.
__device__ __forceinline__ float gelu_exact(float x) {
    return 0.5f * x * (1.0f + erff(x * 0.70710678118654752440f));
}
__device__ __forceinline__ void cpasync16(void* smem, const void* g) {
    uint32_t s = (uint32_t)__cvta_generic_to_shared(smem);
    asm volatile("cp.async.cg.shared.global [%0], [%1], 16;\n" :: "r"(s), "l"(g));
}
__device__ __forceinline__ void cp_commit() {
    asm volatile("cp.async.commit_group;\n");
}
template<int N> __device__ __forceinline__ void cp_wait() {
    asm volatile("cp.async.wait_group %0;\n" :: "n"(N));
}
__device__ __forceinline__ uint32_t f2tf32(float x) {
    uint32_t r; asm("cvt.rna.tf32.f32 %0, %1;\n" : "=r"(r) : "f"(x)); return r;
}
__device__ __forceinline__ void mma_tf32(float* d, const uint32_t* a,
                                         const uint32_t* b) {
    asm volatile(
      "mma.sync.aligned.m16n8k8.row.col.f32.tf32.tf32.f32 "
      "{%0,%1,%2,%3},{%4,%5,%6,%7},{%8,%9},{%0,%1,%2,%3};\n"
      : "+f"(d[0]), "+f"(d[1]), "+f"(d[2]), "+f"(d[3])
      : "r"(a[0]), "r"(a[1]), "r"(a[2]), "r"(a[3]), "r"(b[0]), "r"(b[1]));
}

#define ASTRIDE 20      // 16 + 4 pad  (conflict-free frag loads)
#define BSTRIDE 136     // 128 + 8 pad (conflict-free frag loads, NN)

template<int BMODE, int EPI>
__global__ void __launch_bounds__(128) gemm_tc(
    const float* __restrict__ A, const float* __restrict__ B,
    const float* __restrict__ bias, float* __restrict__ C,
    int M, int Nc, int K)
{
    constexpr int SBSZ = (BMODE == 0) ? 16*BSTRIDE : 128*ASTRIDE;
    __shared__ float As[2][128*ASTRIDE];
    __shared__ float Bs[2][SBSZ];

    const int t    = threadIdx.x;
    const int lane = t & 31;
    const int wid  = t >> 5;
    const int wm   = (wid >> 1) * 64;   // warp m offset in CTA tile
    const int wn   = (wid & 1) * 64;    // warp n offset
    const int g    = lane >> 2;         // group id 0..7
    const int tg   = lane & 3;          // thread-in-group 0..3

    const int bm = blockIdx.y * 128;
    const int bn = blockIdx.x * 128;

    float acc[4][8][4];
    #pragma unroll
    for (int i = 0; i < 4; i++)
        #pragma unroll
        for (int j = 0; j < 8; j++)
            #pragma unroll
            for (int v = 0; v < 4; v++) acc[i][j][v] = 0.f;

    // ---- async tile loaders ----
    const int ar = t >> 2;            // base row for A copies
    const int akc = (t & 3) * 4;      // k-chunk offset (floats)
    auto loadA = [&](int buf, int k0) {
        #pragma unroll
        for (int i = 0; i < 4; i++) {
            int r = ar + 32*i;
            cpasync16(&As[buf][r*ASTRIDE + akc],
                      A + (size_t)(bm + r)*K + k0 + akc);
        }
    };
    auto loadB = [&](int buf, int k0) {
        if (BMODE == 0) {
            int bk = t >> 5;          // 0..3
            int nc = (t & 31) * 4;    // n-chunk (floats)
            #pragma unroll
            for (int i = 0; i < 4; i++) {
                int k = bk + 4*i;
                cpasync16(&Bs[buf][k*BSTRIDE + nc],
                          B + (size_t)(k0 + k)*Nc + bn + nc);
            }
        } else {
            #pragma unroll
            for (int i = 0; i < 4; i++) {
                int n = ar + 32*i;
                cpasync16(&Bs[buf][n*ASTRIDE + akc],
                          B + (size_t)(bn + n)*K + k0 + akc);
            }
        }
    };

    const int niter = K / 16;
    loadA(0, 0); loadB(0, 0); cp_commit();

    for (int it = 0; it < niter; ++it) {
        int buf = it & 1;
        if (it + 1 < niter) {
            loadA(buf ^ 1, (it + 1) * 16);
            loadB(buf ^ 1, (it + 1) * 16);
            cp_commit();
            cp_wait<1>();
        } else {
            cp_wait<0>();
        }
        __syncthreads();

        #pragma unroll
        for (int ks = 0; ks < 16; ks += 8) {
            uint32_t af[4][4];
            #pragma unroll
            for (int mt = 0; mt < 4; mt++) {
                int idx = (wm + mt*16 + g)*ASTRIDE + ks + tg;
                af[mt][0] = f2tf32(As[buf][idx]);
                af[mt][1] = f2tf32(As[buf][idx + 8*ASTRIDE]);
                af[mt][2] = f2tf32(As[buf][idx + 4]);
                af[mt][3] = f2tf32(As[buf][idx + 8*ASTRIDE + 4]);
            }
            uint32_t bf[8][2];
            #pragma unroll
            for (int nt = 0; nt < 8; nt++) {
                if (BMODE == 0) {
                    int idx = (ks + tg)*BSTRIDE + wn + nt*8 + g;
                    bf[nt][0] = f2tf32(Bs[buf][idx]);
                    bf[nt][1] = f2tf32(Bs[buf][idx + 4*BSTRIDE]);
                } else {
                    int idx = (wn + nt*8 + g)*ASTRIDE + ks + tg;
                    bf[nt][0] = f2tf32(Bs[buf][idx]);
                    bf[nt][1] = f2tf32(Bs[buf][idx + 4]);
                }
            }
            #pragma unroll
            for (int mt = 0; mt < 4; mt++)
                #pragma unroll
                for (int nt = 0; nt < 8; nt++)
                    mma_tf32(acc[mt][nt], af[mt], bf[nt]);
        }
        __syncthreads();
    }

    // ---- epilogue ----
    #pragma unroll
    for (int nt = 0; nt < 8; nt++) {
        int c = bn + wn + nt*8 + tg*2;
        float bv0 = 0.f, bv1 = 0.f;
        if (EPI != 0) { bv0 = bias[c]; bv1 = bias[c+1]; }
        #pragma unroll
        for (int mt = 0; mt < 4; mt++) {
            int r = bm + wm + mt*16 + g;
            float* p0 = C + (size_t)r*Nc + c;
            float* p1 = C + (size_t)(r+8)*Nc + c;
            if (EPI == 0) {
                *(float2*)p0 = make_float2(acc[mt][nt][0], acc[mt][nt][1]);
                *(float2*)p1 = make_float2(acc[mt][nt][2], acc[mt][nt][3]);
            } else if (EPI == 1) {
                *(float2*)p0 = make_float2(gelu_exact(acc[mt][nt][0] + bv0),
                                           gelu_exact(acc[mt][nt][1] + bv1));
                *(float2*)p1 = make_float2(gelu_exact(acc[mt][nt][2] + bv0),
                                           gelu_exact(acc[mt][nt][3] + bv1));
            } else {
                float2 o0 = *(float2*)p0, o1 = *(float2*)p1;
                o0.x += acc[mt][nt][0] + bv0; o0.y += acc[mt][nt][1] + bv1;
                o1.x += acc[mt][nt][2] + bv0; o1.y += acc[mt][nt][3] + bv1;
                *(float2*)p0 = o0;
                *(float2*)p1 = o1;
            }
        }
    }
}

// ---------------- driver ----------------
extern "C" void kernel_launch(void* const* d_in, const int* in_sizes, int n_in,
                              void* d_out, int out_size)
{
    const int*   tokens = (const int*)  d_in[0];
    const float* emb    = (const float*)d_in[1];
    const float* ln1_w  = (const float*)d_in[2];
    const float* ln1_b  = (const float*)d_in[3];
    const float* A_log  = (const float*)d_in[4];
    const float* Bm     = (const float*)d_in[5];
    const float* Cm     = (const float*)d_in[6];
    const float* log_dt = (const float*)d_in[7];
    const float* ln2_w  = (const float*)d_in[8];
    const float* ln2_b  = (const float*)d_in[9];
    const float* W1     = (const float*)d_in[10];
    const float* b1     = (const float*)d_in[11];
    const float* W2     = (const float*)d_in[12];
    const float* b2     = (const float*)d_in[13];
    const float* lnf_w  = (const float*)d_in[14];
    const float* lnf_b  = (const float*)d_in[15];
    float* out = (float*)d_out;

    float *ph, *px, *pxT, *pmid;
    cudaGetSymbolAddress((void**)&ph,   g_h);
    cudaGetSymbolAddress((void**)&px,   g_x);
    cudaGetSymbolAddress((void**)&pxT,  g_xT);
    cudaGetSymbolAddress((void**)&pmid, g_mid);

    // embedding
    embed_kernel<<<(MROWS*HID + 255)/256, 256>>>(tokens, emb, ph);

    for (int l = 0; l < NLAYER; l++) {
        // LN1 -> transposed [B,H,S]
        ln_kernel<<<MROWS, 256>>>(ph, pxT, ln1_w + l*HID, ln1_b + l*HID, 1);
        // S4D scan, adds into residual
        s4d_kernel<<<(BATCH*HID*32 + 255)/256, 256>>>(pxT, ph, A_log, Bm, Cm, log_dt, l);
        // LN2 -> normal layout
        ln_kernel<<<MROWS, 256>>>(ph, px, ln2_w + l*HID, ln2_b + l*HID, 0);
        // MLP up: gelu(x @ W1 + b1)
        gemm_tc<0,1><<<dim3(FFN/128, MROWS/128), 128>>>(
            px, W1 + (size_t)l*HID*FFN, b1 + (size_t)l*FFN, pmid, MROWS, FFN, HID);
        // MLP down + residual: h += mid @ W2 + b2
        gemm_tc<0,2><<<dim3(HID/128, MROWS/128), 128>>>(
            pmid, W2 + (size_t)l*FFN*HID, b2 + (size_t)l*HID, ph, MROWS, HID, FFN);
    }

    // final LN + tied head (NT: logits = x @ embed^T)
    ln_kernel<<<MROWS, 256>>>(ph, px, lnf_w, lnf_b, 0);
    gemm_tc<1,0><<<dim3(VOCAB/128, MROWS/128), 128>>>(
        px, emb, nullptr, out, MROWS, VOCAB, HID);
}

// round 4
// speedup vs baseline: 4.2042x; 1.5678x over previous
#include <cuda_runtime.h>
#include <cuda_fp16.h>
#include <math.h>
#include <stdint.h>

// ---------------- problem constants ----------------
#define BATCH   2
#define SEQ     2048
#define HID     768
#define NST     64
#define NLAYER  6
#define VOCAB   32000
#define MROWS   (BATCH*SEQ)          // 4096
#define FFN     (4*HID)              // 3072
#define EPSLN   1e-5f

// ---------------- scratch (device globals; no malloc allowed) ----------------
__device__ float  g_h   [MROWS*HID];          // residual stream [B,S,H] fp32
__device__ __half g_x   [MROWS*HID];          // LN output (fp16, GEMM A)
__device__ float  g_xT  [BATCH*HID*SEQ];      // LN1 output transposed [B,H,S]
__device__ __half g_mid [MROWS*FFN];          // MLP intermediate fp16
__device__ __half g_w1t [NLAYER*FFN*HID];     // W1^T [FFN, HID] fp16
__device__ __half g_w2t [NLAYER*HID*FFN];     // W2^T [HID, FFN] fp16
__device__ __half g_embH[VOCAB*HID];          // embed fp16 [VOCAB, HID]

// ---------------- small helpers ----------------
__device__ __forceinline__ uint32_t smem_u32(const void* p) {
    return (uint32_t)__cvta_generic_to_shared(p);
}
__device__ __forceinline__ float gelu_exact(float x) {
    return 0.5f * x * (1.0f + erff(x * 0.70710678118654752440f));
}
__device__ __forceinline__ void cpasync16(void* smem, const void* g) {
    uint32_t s = smem_u32(smem);
    asm volatile("cp.async.cg.shared.global [%0], [%1], 16;\n" :: "r"(s), "l"(g));
}
__device__ __forceinline__ void cp_commit() { asm volatile("cp.async.commit_group;\n"); }
template<int N> __device__ __forceinline__ void cp_wait() {
    asm volatile("cp.async.wait_group %0;\n" :: "n"(N));
}
__device__ __forceinline__ void mma_f16(float* d, const uint32_t* a, const uint32_t* b) {
    asm volatile(
      "mma.sync.aligned.m16n8k16.row.col.f32.f16.f16.f32 "
      "{%0,%1,%2,%3},{%4,%5,%6,%7},{%8,%9},{%0,%1,%2,%3};\n"
      : "+f"(d[0]), "+f"(d[1]), "+f"(d[2]), "+f"(d[3])
      : "r"(a[0]), "r"(a[1]), "r"(a[2]), "r"(a[3]), "r"(b[0]), "r"(b[1]));
}

// ---------------- embedding gather (fp32 residual) ----------------
__global__ void embed_kernel(const int* __restrict__ tokens,
                             const float* __restrict__ emb,
                             float* __restrict__ out)
{
    int e = blockIdx.x * blockDim.x + threadIdx.x;
    if (e >= MROWS*HID) return;
    int row = e / HID, c = e - row*HID;
    out[e] = emb[(size_t)tokens[row]*HID + c];
}

// ---------------- fp32 -> fp16 copy ----------------
__global__ void f2h_kernel(const float4* __restrict__ s, __half2* __restrict__ d, int n4)
{
    int i = blockIdx.x * blockDim.x + threadIdx.x;
    if (i >= n4) return;
    float4 v = s[i];
    d[2*i]   = __floats2half2_rn(v.x, v.y);
    d[2*i+1] = __floats2half2_rn(v.z, v.w);
}

// ---------------- transpose fp32[R,C] -> fp16[C,R] (per layer z) ----------
__global__ void transpose_h(const float* __restrict__ src, __half* __restrict__ dst,
                            int R, int Cc)
{
    __shared__ float t[32][33];
    const float* s = src + (size_t)blockIdx.z * R * Cc;
    __half*      d = dst + (size_t)blockIdx.z * R * Cc;
    int c0 = blockIdx.x * 32, r0 = blockIdx.y * 32;
    int tx = threadIdx.x, ty = threadIdx.y;
    #pragma unroll
    for (int j = 0; j < 32; j += 8)
        t[ty+j][tx] = s[(size_t)(r0+ty+j)*Cc + c0 + tx];
    __syncthreads();
    #pragma unroll
    for (int j = 0; j < 32; j += 8)
        d[(size_t)(c0+ty+j)*R + r0 + tx] = __float2half_rn(t[tx][ty+j]);
}

// ---------------- layernorm ----------------
// MODE 0: write fp16 [B,S,H] (feeds GEMM A). MODE 1: write fp32 [B,H,S] (scan).
template<int MODE>
__global__ void ln_kernel(const float* __restrict__ in, void* __restrict__ outv,
                          const float* __restrict__ w, const float* __restrict__ b)
{
    int row = blockIdx.x;
    int tid = threadIdx.x;
    const float* xr = in + (size_t)row*HID;
    float x0 = xr[tid], x1 = xr[tid+256], x2 = xr[tid+512];

    __shared__ float red[256];
    red[tid] = x0 + x1 + x2;
    __syncthreads();
    #pragma unroll
    for (int s = 128; s > 0; s >>= 1) {
        if (tid < s) red[tid] += red[tid+s];
        __syncthreads();
    }
    float mean = red[0] * (1.0f/HID);
    __syncthreads();

    float d0 = x0-mean, d1 = x1-mean, d2 = x2-mean;
    red[tid] = d0*d0 + d1*d1 + d2*d2;
    __syncthreads();
    #pragma unroll
    for (int s = 128; s > 0; s >>= 1) {
        if (tid < s) red[tid] += red[tid+s];
        __syncthreads();
    }
    float rstd = rsqrtf(red[0]*(1.0f/HID) + EPSLN);

    float o0 = d0*rstd*w[tid    ] + b[tid    ];
    float o1 = d1*rstd*w[tid+256] + b[tid+256];
    float o2 = d2*rstd*w[tid+512] + b[tid+512];

    if (MODE == 0) {
        __half* orow = (__half*)outv + (size_t)row*HID;
        orow[tid]     = __float2half_rn(o0);
        orow[tid+256] = __float2half_rn(o1);
        orow[tid+512] = __float2half_rn(o2);
    } else {
        float* out = (float*)outv;
        int bb = row / SEQ, t = row - bb*SEQ;
        size_t base = (size_t)bb*HID*SEQ + t;
        out[base + (size_t)(tid    )*SEQ] = o0;
        out[base + (size_t)(tid+256)*SEQ] = o1;
        out[base + (size_t)(tid+512)*SEQ] = o2;
    }
}

// ---------------- S4D scan: one warp per (b,h); 2 states per lane -----------
__global__ void __launch_bounds__(256) s4d_kernel(
    const float* __restrict__ xT, float* __restrict__ hres,
    const float* __restrict__ A_log, const float* __restrict__ Bm,
    const float* __restrict__ Cm, const float* __restrict__ log_dt, int layer)
{
    int gwarp = (blockIdx.x * blockDim.x + threadIdx.x) >> 5;
    int lane  = threadIdx.x & 31;
    int w     = threadIdx.x >> 5;
    if (gwarp >= BATCH*HID) return;
    int b = gwarp / HID, h = gwarp - b*HID;

    float dtv = expf(log_dt[layer*HID + h]);
    int n0 = lane, n1 = lane + 32;
    float A0 = expf(-dtv * expf(A_log[layer*NST + n0]));
    float A1 = expf(-dtv * expf(A_log[layer*NST + n1]));
    size_t pbase = ((size_t)layer*HID + h) * NST;
    float B0 = dtv * Bm[pbase + n0];
    float B1 = dtv * Bm[pbase + n1];
    float C0 = Cm[pbase + n0];
    float C1 = Cm[pbase + n1];

    __shared__ float sh[8][32][33];

    const float* xrow = xT + ((size_t)b*HID + h) * SEQ;
    float*       hout = hres + (size_t)b*SEQ*HID + h;

    float s0 = 0.f, s1 = 0.f;
    for (int t0 = 0; t0 < SEQ; t0 += 32) {
        float xv = xrow[t0 + lane];
        #pragma unroll
        for (int i = 0; i < 32; i++) {
            float xt = __shfl_sync(0xffffffffu, xv, i);
            s0 = fmaf(A0, s0, B0 * xt);
            s1 = fmaf(A1, s1, B1 * xt);
            sh[w][i][lane] = fmaf(s0, C0, s1 * C1);
        }
        __syncwarp();
        float acc = 0.f;
        #pragma unroll
        for (int j = 0; j < 32; j++) acc += sh[w][lane][j];
        hout[(size_t)(t0 + lane) * HID] += acc;
        __syncwarp();
    }
}

// ---------------- fp16 tensor-core GEMM --------------------------------------
// C[M,Nc] = A[M,K] @ Bt^T ; A [M,K] fp16 row-major, Bt [Nc,K] fp16 row-major.
// CTA 128x128, BK=32 halves, 4 warps (warp tile 64x64), double-buffered
// cp.async, padded k-major smem (row stride 40 halves -> conflict-free frags).
// EPI 0: C(f32) = acc. EPI 1: C(f16) = gelu(acc+bias). EPI 2: C(f32) += acc+bias.
#define BKH 32
#define RSH 40       // halves per smem row (32 data + 8 pad)

template<int EPI>
__global__ void __launch_bounds__(128) gemm_h(
    const __half* __restrict__ A, const __half* __restrict__ Bt,
    const float* __restrict__ bias, void* __restrict__ Cv,
    int M, int Nc, int K)
{
    __shared__ __half As[2][128*RSH];
    __shared__ __half Bs[2][128*RSH];

    const int tid  = threadIdx.x;
    const int lane = tid & 31;
    const int wid  = tid >> 5;
    const int wm   = (wid >> 1) * 64;
    const int wn   = (wid & 1) * 64;
    const int g    = lane >> 2;     // 0..7
    const int tg   = lane & 3;      // 0..3

    const int bm = blockIdx.x * 128;
    const int bn = blockIdx.y * 128;

    float acc[4][8][4];
    #pragma unroll
    for (int i = 0; i < 4; i++)
        #pragma unroll
        for (int j = 0; j < 8; j++)
            #pragma unroll
            for (int v = 0; v < 4; v++) acc[i][j][v] = 0.f;

    auto load_stage = [&](int buf, int k0) {
        #pragma unroll
        for (int j = 0; j < 4; j++) {
            int c  = tid + 128*j;        // 0..511
            int r  = c >> 2;             // 0..127
            int ch = (c & 3) * 8;        // halves offset within row
            cpasync16(&As[buf][r*RSH + ch], A  + (size_t)(bm + r)*K + k0 + ch);
            cpasync16(&Bs[buf][r*RSH + ch], Bt + (size_t)(bn + r)*K + k0 + ch);
        }
    };

    const int niter = K / BKH;
    load_stage(0, 0); cp_commit();

    for (int it = 0; it < niter; ++it) {
        int buf = it & 1;
        if (it + 1 < niter) {
            load_stage(buf ^ 1, (it + 1) * BKH);
            cp_commit();
            cp_wait<1>();
        } else {
            cp_wait<0>();
        }
        __syncthreads();

        const uint32_t* As32 = (const uint32_t*)&As[buf][0];
        const uint32_t* Bs32 = (const uint32_t*)&Bs[buf][0];

        #pragma unroll
        for (int ks = 0; ks < BKH; ks += 16) {
            uint32_t af[4][4];
            #pragma unroll
            for (int mt = 0; mt < 4; mt++) {
                int r0 = (wm + mt*16 + g) * RSH + ks + 2*tg;
                int r1 = r0 + 8*RSH;
                af[mt][0] = As32[r0 >> 1];
                af[mt][1] = As32[r1 >> 1];
                af[mt][2] = As32[(r0 + 8) >> 1];
                af[mt][3] = As32[(r1 + 8) >> 1];
            }
            uint32_t bf[8][2];
            #pragma unroll
            for (int nt = 0; nt < 8; nt++) {
                int r = (wn + nt*8 + g) * RSH + ks + 2*tg;
                bf[nt][0] = Bs32[r >> 1];
                bf[nt][1] = Bs32[(r + 8) >> 1];
            }
            #pragma unroll
            for (int mt = 0; mt < 4; mt++)
                #pragma unroll
                for (int nt = 0; nt < 8; nt++)
                    mma_f16(acc[mt][nt], af[mt], bf[nt]);
        }
        __syncthreads();
    }

    // ---- epilogue ----
    #pragma unroll
    for (int nt = 0; nt < 8; nt++) {
        const int c = bn + wn + nt*8 + 2*tg;
        float bv0 = 0.f, bv1 = 0.f;
        if (EPI != 0) { bv0 = bias[c]; bv1 = bias[c+1]; }
        #pragma unroll
        for (int mt = 0; mt < 4; mt++) {
            const int r0 = bm + wm + mt*16 + g;
            if (EPI == 0) {
                float* C = (float*)Cv;
                *(float2*)(C + (size_t)r0*Nc + c)     = make_float2(acc[mt][nt][0], acc[mt][nt][1]);
                *(float2*)(C + (size_t)(r0+8)*Nc + c) = make_float2(acc[mt][nt][2], acc[mt][nt][3]);
            } else if (EPI == 1) {
                __half* C = (__half*)Cv;
                *(__half2*)(C + (size_t)r0*Nc + c) =
                    __floats2half2_rn(gelu_exact(acc[mt][nt][0] + bv0),
                                      gelu_exact(acc[mt][nt][1] + bv1));
                *(__half2*)(C + (size_t)(r0+8)*Nc + c) =
                    __floats2half2_rn(gelu_exact(acc[mt][nt][2] + bv0),
                                      gelu_exact(acc[mt][nt][3] + bv1));
            } else {
                float* C = (float*)Cv;
                float2 o0 = *(float2*)(C + (size_t)r0*Nc + c);
                float2 o1 = *(float2*)(C + (size_t)(r0+8)*Nc + c);
                o0.x += acc[mt][nt][0] + bv0; o0.y += acc[mt][nt][1] + bv1;
                o1.x += acc[mt][nt][2] + bv0; o1.y += acc[mt][nt][3] + bv1;
                *(float2*)(C + (size_t)r0*Nc + c)     = o0;
                *(float2*)(C + (size_t)(r0+8)*Nc + c) = o1;
            }
        }
    }
}

// ---------------- driver ----------------
extern "C" void kernel_launch(void* const* d_in, const int* in_sizes, int n_in,
                              void* d_out, int out_size)
{
    const int*   tokens = (const int*)  d_in[0];
    const float* emb    = (const float*)d_in[1];
    const float* ln1_w  = (const float*)d_in[2];
    const float* ln1_b  = (const float*)d_in[3];
    const float* A_log  = (const float*)d_in[4];
    const float* Bm     = (const float*)d_in[5];
    const float* Cm     = (const float*)d_in[6];
    const float* log_dt = (const float*)d_in[7];
    const float* W1     = (const float*)d_in[10];
    const float* b1     = (const float*)d_in[11];
    const float* W2     = (const float*)d_in[12];
    const float* b2     = (const float*)d_in[13];
    const float* ln2_w  = (const float*)d_in[8];
    const float* ln2_b  = (const float*)d_in[9];
    const float* lnf_w  = (const float*)d_in[14];
    const float* lnf_b  = (const float*)d_in[15];
    float* out = (float*)d_out;

    float  *ph, *pxT;
    __half *px, *pmid, *pw1t, *pw2t, *pembH;
    cudaGetSymbolAddress((void**)&ph,    g_h);
    cudaGetSymbolAddress((void**)&px,    g_x);
    cudaGetSymbolAddress((void**)&pxT,   g_xT);
    cudaGetSymbolAddress((void**)&pmid,  g_mid);
    cudaGetSymbolAddress((void**)&pw1t,  g_w1t);
    cudaGetSymbolAddress((void**)&pw2t,  g_w2t);
    cudaGetSymbolAddress((void**)&pembH, g_embH);

    // embedding gather (fp32 residual)
    embed_kernel<<<(MROWS*HID + 255)/256, 256>>>(tokens, emb, ph);

    // weight prep: transpose->fp16 W1, W2; fp16 copy of embed
    transpose_h<<<dim3(FFN/32, HID/32, NLAYER), dim3(32,8)>>>(W1, pw1t, HID, FFN);
    transpose_h<<<dim3(HID/32, FFN/32, NLAYER), dim3(32,8)>>>(W2, pw2t, FFN, HID);
    f2h_kernel<<<(VOCAB*HID/4 + 255)/256, 256>>>((const float4*)emb, (__half2*)pembH, VOCAB*HID/4);

    for (int l = 0; l < NLAYER; l++) {
        ln_kernel<1><<<MROWS, 256>>>(ph, pxT, ln1_w + l*HID, ln1_b + l*HID);
        s4d_kernel<<<(BATCH*HID*32 + 255)/256, 256>>>(pxT, ph, A_log, Bm, Cm, log_dt, l);
        ln_kernel<0><<<MROWS, 256>>>(ph, px, ln2_w + l*HID, ln2_b + l*HID);
        // mid = fp16(gelu(x @ W1 + b1)) : Bt = W1T [FFN, HID]
        gemm_h<1><<<dim3(MROWS/128, FFN/128), 128>>>(
            px, pw1t + (size_t)l*FFN*HID, b1 + (size_t)l*FFN, pmid, MROWS, FFN, HID);
        // h += mid @ W2 + b2 : Bt = W2T [HID, FFN]
        gemm_h<2><<<dim3(MROWS/128, HID/128), 128>>>(
            pmid, pw2t + (size_t)l*HID*FFN, b2 + (size_t)l*HID, ph, MROWS, HID, FFN);
    }

    // final LN + tied head: logits = x @ embed^T (fp32 out)
    ln_kernel<0><<<MROWS, 256>>>(ph, px, lnf_w, lnf_b);
    gemm_h<0><<<dim3(MROWS/128, VOCAB/128), 128>>>(
        px, pembH, nullptr, out, MROWS, VOCAB, HID);
}

// round 5
// speedup vs baseline: 4.8458x; 1.1526x over previous
#include <cuda_runtime.h>
#include <cuda_fp16.h>
#include <math.h>
#include <stdint.h>

// ---------------- problem constants ----------------
#define BATCH   2
#define SEQ     2048
#define HID     768
#define NST     64
#define NLAYER  6
#define VOCAB   32000
#define MROWS   (BATCH*SEQ)          // 4096
#define FFN     (4*HID)              // 3072
#define EPSLN   1e-5f

// ---------------- scratch (device globals; no malloc allowed) ----------------
__device__ float  g_h   [MROWS*HID];          // residual stream [B,S,H] fp32
__device__ __half g_x   [MROWS*HID];          // LN output (fp16, GEMM A)
__device__ float  g_xT  [BATCH*HID*SEQ];      // LN1 output transposed [B,H,S]
__device__ __half g_mid [MROWS*FFN];          // MLP intermediate fp16
__device__ __half g_w1t [NLAYER*FFN*HID];     // W1^T [FFN, HID] fp16
__device__ __half g_w2t [NLAYER*HID*FFN];     // W2^T [HID, FFN] fp16
__device__ __half g_embH[VOCAB*HID];          // embed fp16 [VOCAB, HID]

// ---------------- small helpers ----------------
__device__ __forceinline__ uint32_t smem_u32(const void* p) {
    return (uint32_t)__cvta_generic_to_shared(p);
}
__device__ __forceinline__ float gelu_exact(float x) {
    return 0.5f * x * (1.0f + erff(x * 0.70710678118654752440f));
}
__device__ __forceinline__ void cpasync16(void* smem, const void* g) {
    uint32_t s = smem_u32(smem);
    asm volatile("cp.async.cg.shared.global [%0], [%1], 16;\n" :: "r"(s), "l"(g));
}
__device__ __forceinline__ void cp_commit() { asm volatile("cp.async.commit_group;\n"); }
template<int N> __device__ __forceinline__ void cp_wait() {
    asm volatile("cp.async.wait_group %0;\n" :: "n"(N));
}
__device__ __forceinline__ void mma_f16(float* d, const uint32_t* a, const uint32_t* b) {
    asm volatile(
      "mma.sync.aligned.m16n8k16.row.col.f32.f16.f16.f32 "
      "{%0,%1,%2,%3},{%4,%5,%6,%7},{%8,%9},{%0,%1,%2,%3};\n"
      : "+f"(d[0]), "+f"(d[1]), "+f"(d[2]), "+f"(d[3])
      : "r"(a[0]), "r"(a[1]), "r"(a[2]), "r"(a[3]), "r"(b[0]), "r"(b[1]));
}
__device__ __forceinline__ void ldmx4(uint32_t* r, uint32_t addr) {
    asm volatile("ldmatrix.sync.aligned.m8n8.x4.shared.b16 {%0,%1,%2,%3}, [%4];"
        : "=r"(r[0]), "=r"(r[1]), "=r"(r[2]), "=r"(r[3]) : "r"(addr));
}

// ---------------- embedding gather (fp32 residual) ----------------
__global__ void embed_kernel(const int* __restrict__ tokens,
                             const float* __restrict__ emb,
                             float* __restrict__ out)
{
    int e = blockIdx.x * blockDim.x + threadIdx.x;
    if (e >= MROWS*HID) return;
    int row = e / HID, c = e - row*HID;
    out[e] = emb[(size_t)tokens[row]*HID + c];
}

// ---------------- fp32 -> fp16 copy ----------------
__global__ void f2h_kernel(const float4* __restrict__ s, __half2* __restrict__ d, int n4)
{
    int i = blockIdx.x * blockDim.x + threadIdx.x;
    if (i >= n4) return;
    float4 v = s[i];
    d[2*i]   = __floats2half2_rn(v.x, v.y);
    d[2*i+1] = __floats2half2_rn(v.z, v.w);
}

// ---------------- transpose fp32[R,C] -> fp16[C,R] (per layer z) ----------
__global__ void transpose_h(const float* __restrict__ src, __half* __restrict__ dst,
                            int R, int Cc)
{
    __shared__ float t[32][33];
    const float* s = src + (size_t)blockIdx.z * R * Cc;
    __half*      d = dst + (size_t)blockIdx.z * R * Cc;
    int c0 = blockIdx.x * 32, r0 = blockIdx.y * 32;
    int tx = threadIdx.x, ty = threadIdx.y;
    #pragma unroll
    for (int j = 0; j < 32; j += 8)
        t[ty+j][tx] = s[(size_t)(r0+ty+j)*Cc + c0 + tx];
    __syncthreads();
    #pragma unroll
    for (int j = 0; j < 32; j += 8)
        d[(size_t)(c0+ty+j)*R + r0 + tx] = __float2half_rn(t[tx][ty+j]);
}

// ---------------- layernorm: one warp per row (H=768 -> 12 float2/lane) -----
// MODE 0: write fp16 [B,S,H]. MODE 1: write fp32 [B,H,S] (transposed, scan).
template<int MODE>
__global__ void __launch_bounds__(256) ln_kernel(
    const float* __restrict__ in, void* __restrict__ outv,
    const float* __restrict__ w, const float* __restrict__ b)
{
    const int lane = threadIdx.x & 31;
    const int row  = blockIdx.x * 8 + (threadIdx.x >> 5);
    const float2* xr = (const float2*)(in + (size_t)row*HID);
    const float2* w2 = (const float2*)w;
    const float2* b2 = (const float2*)b;

    float2 v[12];
    float sum = 0.f;
    #pragma unroll
    for (int i = 0; i < 12; i++) {
        v[i] = xr[lane + 32*i];
        sum += v[i].x + v[i].y;
    }
    #pragma unroll
    for (int o = 16; o > 0; o >>= 1) sum += __shfl_xor_sync(0xffffffffu, sum, o);
    float mean = sum * (1.0f/HID);

    float vs = 0.f;
    #pragma unroll
    for (int i = 0; i < 12; i++) {
        float dx = v[i].x - mean, dy = v[i].y - mean;
        vs += dx*dx + dy*dy;
    }
    #pragma unroll
    for (int o = 16; o > 0; o >>= 1) vs += __shfl_xor_sync(0xffffffffu, vs, o);
    float rstd = rsqrtf(vs * (1.0f/HID) + EPSLN);

    if (MODE == 0) {
        __half2* orow = (__half2*)outv + (size_t)row*(HID/2);
        #pragma unroll
        for (int i = 0; i < 12; i++) {
            int c = lane + 32*i;
            float2 ww = w2[c], bb = b2[c];
            float o0 = (v[i].x - mean)*rstd*ww.x + bb.x;
            float o1 = (v[i].y - mean)*rstd*ww.y + bb.y;
            orow[c] = __floats2half2_rn(o0, o1);
        }
    } else {
        float* out = (float*)outv;
        int bbi = row / SEQ, t = row - bbi*SEQ;
        size_t base = (size_t)bbi*HID*SEQ + t;
        #pragma unroll
        for (int i = 0; i < 12; i++) {
            int c = lane + 32*i;
            float2 ww = w2[c], bb = b2[c];
            out[base + (size_t)(2*c  )*SEQ] = (v[i].x - mean)*rstd*ww.x + bb.x;
            out[base + (size_t)(2*c+1)*SEQ] = (v[i].y - mean)*rstd*ww.y + bb.y;
        }
    }
}

// ---------------- S4D scan: one warp per (b,h); 2 states per lane -----------
__global__ void __launch_bounds__(256) s4d_kernel(
    const float* __restrict__ xT, float* __restrict__ hres,
    const float* __restrict__ A_log, const float* __restrict__ Bm,
    const float* __restrict__ Cm, const float* __restrict__ log_dt, int layer)
{
    int gwarp = (blockIdx.x * blockDim.x + threadIdx.x) >> 5;
    int lane  = threadIdx.x & 31;
    int w     = threadIdx.x >> 5;
    if (gwarp >= BATCH*HID) return;
    int b = gwarp / HID, h = gwarp - b*HID;

    float dtv = expf(log_dt[layer*HID + h]);
    int n0 = lane, n1 = lane + 32;
    float A0 = expf(-dtv * expf(A_log[layer*NST + n0]));
    float A1 = expf(-dtv * expf(A_log[layer*NST + n1]));
    size_t pbase = ((size_t)layer*HID + h) * NST;
    float B0 = dtv * Bm[pbase + n0];
    float B1 = dtv * Bm[pbase + n1];
    float C0 = Cm[pbase + n0];
    float C1 = Cm[pbase + n1];

    __shared__ float sh[8][32][33];

    const float* xrow = xT + ((size_t)b*HID + h) * SEQ;
    float*       hout = hres + (size_t)b*SEQ*HID + h;

    float s0 = 0.f, s1 = 0.f;
    for (int t0 = 0; t0 < SEQ; t0 += 32) {
        float xv = xrow[t0 + lane];
        #pragma unroll
        for (int i = 0; i < 32; i++) {
            float xt = __shfl_sync(0xffffffffu, xv, i);
            s0 = fmaf(A0, s0, B0 * xt);
            s1 = fmaf(A1, s1, B1 * xt);
            sh[w][i][lane] = fmaf(s0, C0, s1 * C1);
        }
        __syncwarp();
        float acc = 0.f;
        #pragma unroll
        for (int j = 0; j < 32; j++) acc += sh[w][lane][j];
        hout[(size_t)(t0 + lane) * HID] += acc;
        __syncwarp();
    }
}

// ---------------- fp16 tensor-core GEMM (ldmatrix + 8 warps) -----------------
// C[M,Nc] = A[M,K] @ Bt^T ; A [M,K] fp16 row-major, Bt [Nc,K] fp16 row-major.
// CTA 128x128, BK=64 halves, 8 warps (warp tile 32x64), double-buffered
// cp.async, padded k-major smem (stride 72 halves -> ldmatrix conflict-free).
// EPI 0: C(f32)=acc. EPI 1: C(f16)=gelu(acc+bias). EPI 2: C(f32)+=acc+bias.
#define BKH 64
#define RSH 72                        // halves per smem row (64 data + 8 pad)
#define TILEH (128*RSH)               // halves per tile buffer
#define GSMEM (4*TILEH*2)             // bytes: 2 stages x (A+B)

template<int EPI>
__global__ void __launch_bounds__(256) gemm_h(
    const __half* __restrict__ A, const __half* __restrict__ Bt,
    const float* __restrict__ bias, void* __restrict__ Cv,
    int M, int Nc, int K)
{
    extern __shared__ __half sm[];
    __half* Abuf[2] = { sm,             sm + 2*TILEH };
    __half* Bbuf[2] = { sm + TILEH,     sm + 3*TILEH };

    const int tid  = threadIdx.x;
    const int lane = tid & 31;
    const int wid  = tid >> 5;
    const int wm   = (wid >> 1) * 32;
    const int wn   = (wid & 1) * 64;
    const int g    = lane >> 2;
    const int tg   = lane & 3;

    const int bm = blockIdx.x * 128;
    const int bn = blockIdx.y * 128;

    float acc[2][8][4];
    #pragma unroll
    for (int i = 0; i < 2; i++)
        #pragma unroll
        for (int j = 0; j < 8; j++)
            #pragma unroll
            for (int v = 0; v < 4; v++) acc[i][j][v] = 0.f;

    auto load_stage = [&](int buf, int k0) {
        #pragma unroll
        for (int j = 0; j < 4; j++) {
            int c  = tid + 256*j;        // 0..1023
            int r  = c >> 3;             // row 0..127
            int ch = (c & 7) * 8;        // halves within row
            cpasync16(&Abuf[buf][r*RSH + ch], A  + (size_t)(bm + r)*K + k0 + ch);
            cpasync16(&Bbuf[buf][r*RSH + ch], Bt + (size_t)(bn + r)*K + k0 + ch);
        }
    };

    // ldmatrix per-thread address offsets (in halves, within tile)
    const int arow = wm + ((lane >> 3) & 1) * 8 + (lane & 7);
    const int akof = ((lane >> 4) & 1) * 8;
    const int brow = wn + ((lane >> 4) & 1) * 8 + (lane & 7);
    const int bkof = ((lane >> 3) & 1) * 8;

    const int niter = K / BKH;
    load_stage(0, 0); cp_commit();

    for (int it = 0; it < niter; ++it) {
        int buf = it & 1;
        if (it + 1 < niter) {
            load_stage(buf ^ 1, (it + 1) * BKH);
            cp_commit();
            cp_wait<1>();
        } else {
            cp_wait<0>();
        }
        __syncthreads();

        const uint32_t aBase = smem_u32(Abuf[buf]) + (uint32_t)(arow*RSH + akof)*2;
        const uint32_t bBase = smem_u32(Bbuf[buf]) + (uint32_t)(brow*RSH + bkof)*2;

        #pragma unroll
        for (int ks = 0; ks < BKH; ks += 16) {
            uint32_t af[2][4];
            #pragma unroll
            for (int mt = 0; mt < 2; mt++)
                ldmx4(af[mt], aBase + (uint32_t)(mt*16*RSH + ks)*2);
            uint32_t bf[8][2];
            #pragma unroll
            for (int p = 0; p < 4; p++) {
                uint32_t tmp[4];
                ldmx4(tmp, bBase + (uint32_t)(p*16*RSH + ks)*2);
                bf[2*p  ][0] = tmp[0]; bf[2*p  ][1] = tmp[1];
                bf[2*p+1][0] = tmp[2]; bf[2*p+1][1] = tmp[3];
            }
            #pragma unroll
            for (int mt = 0; mt < 2; mt++)
                #pragma unroll
                for (int nt = 0; nt < 8; nt++)
                    mma_f16(acc[mt][nt], af[mt], bf[nt]);
        }
        __syncthreads();
    }

    // ---- epilogue ----
    #pragma unroll
    for (int nt = 0; nt < 8; nt++) {
        const int c = bn + wn + nt*8 + 2*tg;
        float bv0 = 0.f, bv1 = 0.f;
        if (EPI != 0) { bv0 = bias[c]; bv1 = bias[c+1]; }
        #pragma unroll
        for (int mt = 0; mt < 2; mt++) {
            const int r0 = bm + wm + mt*16 + g;
            if (EPI == 0) {
                float* C = (float*)Cv;
                *(float2*)(C + (size_t)r0*Nc + c)     = make_float2(acc[mt][nt][0], acc[mt][nt][1]);
                *(float2*)(C + (size_t)(r0+8)*Nc + c) = make_float2(acc[mt][nt][2], acc[mt][nt][3]);
            } else if (EPI == 1) {
                __half* C = (__half*)Cv;
                *(__half2*)(C + (size_t)r0*Nc + c) =
                    __floats2half2_rn(gelu_exact(acc[mt][nt][0] + bv0),
                                      gelu_exact(acc[mt][nt][1] + bv1));
                *(__half2*)(C + (size_t)(r0+8)*Nc + c) =
                    __floats2half2_rn(gelu_exact(acc[mt][nt][2] + bv0),
                                      gelu_exact(acc[mt][nt][3] + bv1));
            } else {
                float* C = (float*)Cv;
                float2 o0 = *(float2*)(C + (size_t)r0*Nc + c);
                float2 o1 = *(float2*)(C + (size_t)(r0+8)*Nc + c);
                o0.x += acc[mt][nt][0] + bv0; o0.y += acc[mt][nt][1] + bv1;
                o1.x += acc[mt][nt][2] + bv0; o1.y += acc[mt][nt][3] + bv1;
                *(float2*)(C + (size_t)r0*Nc + c)     = o0;
                *(float2*)(C + (size_t)(r0+8)*Nc + c) = o1;
            }
        }
    }
}

// ---------------- driver ----------------
extern "C" void kernel_launch(void* const* d_in, const int* in_sizes, int n_in,
                              void* d_out, int out_size)
{
    const int*   tokens = (const int*)  d_in[0];
    const float* emb    = (const float*)d_in[1];
    const float* ln1_w  = (const float*)d_in[2];
    const float* ln1_b  = (const float*)d_in[3];
    const float* A_log  = (const float*)d_in[4];
    const float* Bm     = (const float*)d_in[5];
    const float* Cm     = (const float*)d_in[6];
    const float* log_dt = (const float*)d_in[7];
    const float* ln2_w  = (const float*)d_in[8];
    const float* ln2_b  = (const float*)d_in[9];
    const float* W1     = (const float*)d_in[10];
    const float* b1     = (const float*)d_in[11];
    const float* W2     = (const float*)d_in[12];
    const float* b2     = (const float*)d_in[13];
    const float* lnf_w  = (const float*)d_in[14];
    const float* lnf_b  = (const float*)d_in[15];
    float* out = (float*)d_out;

    float  *ph, *pxT;
    __half *px, *pmid, *pw1t, *pw2t, *pembH;
    cudaGetSymbolAddress((void**)&ph,    g_h);
    cudaGetSymbolAddress((void**)&px,    g_x);
    cudaGetSymbolAddress((void**)&pxT,   g_xT);
    cudaGetSymbolAddress((void**)&pmid,  g_mid);
    cudaGetSymbolAddress((void**)&pw1t,  g_w1t);
    cudaGetSymbolAddress((void**)&pw2t,  g_w2t);
    cudaGetSymbolAddress((void**)&pembH, g_embH);

    cudaFuncSetAttribute(gemm_h<0>, cudaFuncAttributeMaxDynamicSharedMemorySize, GSMEM);
    cudaFuncSetAttribute(gemm_h<1>, cudaFuncAttributeMaxDynamicSharedMemorySize, GSMEM);
    cudaFuncSetAttribute(gemm_h<2>, cudaFuncAttributeMaxDynamicSharedMemorySize, GSMEM);

    // embedding gather (fp32 residual)
    embed_kernel<<<(MROWS*HID + 255)/256, 256>>>(tokens, emb, ph);

    // weight prep: transpose->fp16 W1, W2; fp16 copy of embed
    transpose_h<<<dim3(FFN/32, HID/32, NLAYER), dim3(32,8)>>>(W1, pw1t, HID, FFN);
    transpose_h<<<dim3(HID/32, FFN/32, NLAYER), dim3(32,8)>>>(W2, pw2t, FFN, HID);
    f2h_kernel<<<(VOCAB*HID/4 + 255)/256, 256>>>((const float4*)emb, (__half2*)pembH, VOCAB*HID/4);

    for (int l = 0; l < NLAYER; l++) {
        ln_kernel<1><<<MROWS/8, 256>>>(ph, pxT, ln1_w + l*HID, ln1_b + l*HID);
        s4d_kernel<<<(BATCH*HID*32 + 255)/256, 256>>>(pxT, ph, A_log, Bm, Cm, log_dt, l);
        ln_kernel<0><<<MROWS/8, 256>>>(ph, px, ln2_w + l*HID, ln2_b + l*HID);
        // mid = fp16(gelu(x @ W1 + b1)) : Bt = W1T [FFN, HID]
        gemm_h<1><<<dim3(MROWS/128, FFN/128), 256, GSMEM>>>(
            px, pw1t + (size_t)l*FFN*HID, b1 + (size_t)l*FFN, pmid, MROWS, FFN, HID);
        // h += mid @ W2 + b2 : Bt = W2T [HID, FFN]
        gemm_h<2><<<dim3(MROWS/128, HID/128), 256, GSMEM>>>(
            pmid, pw2t + (size_t)l*HID*FFN, b2 + (size_t)l*HID, ph, MROWS, HID, FFN);
    }

    // final LN + tied head: logits = x @ embed^T (fp32 out)
    ln_kernel<0><<<MROWS/8, 256>>>(ph, px, lnf_w, lnf_b);
    gemm_h<0><<<dim3(MROWS/128, VOCAB/128), 256, GSMEM>>>(
        px, pembH, nullptr, out, MROWS, VOCAB, HID);
}